// round 9
// baseline (speedup 1.0000x reference)
#include <cuda_runtime.h>
#include <math.h>

// Problem constants (fixed shapes per reference)
#define BDIM    512
#define DEG     16
#define NSLOT   17
#define NREAD   22
#define NEGK    5
#define H       256
#define NNODES  200000
#define HBITS   15
#define HSIZE   (1 << HBITS)
#define HMASK   (HSIZE - 1)
#define HK      16
#define CPR     256
#define NCHUNK  ((NNODES + CPR - 1) / CPR)     // 782
#define NBATCH  (BDIM / 4)                     // 128 step-batches
#define TOTAL_WORK (NBATCH + NCHUNK + BDIM)    // batches, copies, lambda-post
#define NTHR    256
#define FULLMASK 0x1FFFF

// dynamic smem layout (float offsets)
#define ZNB_OFF  0                 // [4][16][256]
#define EMB_OFF  16384             // [4][256]
#define MEAN_OFF 17408             // [4][256]
#define TD_OFF   18432             // [4][17][4]
#define INT_OFF  18704             // ints: s_id, wcnt, wrow[256], we[256]
#define SMEM_FLOATS (INT_OFF + 520)
#define SMEM_BYTES  (SMEM_FLOATS * 4)

// ------------------------- persistent device state -------------------------
__device__ __align__(16) float g_staging[BDIM][NSLOT][H];   // 8.9 MB
// Blocked-transposed weights: g_BT[m][i4*H + h] = float4(W_m[h][4*i4..])
// m: 0=Wh, 1=We2n, 2=Wre, 3=Wrn
__device__ __align__(16) float4 g_BT[4][(H / 4) * H];       // 1 MB
__device__ int g_done[BDIM];
__device__ int g_dirty[NBATCH];        // batch has in-batch dependency
__device__ int g_src[BDIM][NREAD];     // -1 => z0[row], else (t'<<5)|w'
__device__ int g_ctr;
__device__ int g_hrow[HSIZE];
__device__ int g_hcnt[HSIZE];
__device__ int g_hent[HSIZE][HK];      // e = (t<<10)|(prio<<5)|w

// ------------------------------- helpers -----------------------------------
__device__ __forceinline__ unsigned hashrow(int row) {
    return ((unsigned)row * 2654435761u) >> (32 - HBITS);
}
__device__ __forceinline__ int ld_acq(const int* p) {
    int v; asm volatile("ld.acquire.gpu.b32 %0, [%1];" : "=r"(v) : "l"(p) : "memory"); return v;
}
__device__ __forceinline__ void red_or_rel(int* p, int v) {
    asm volatile("red.release.gpu.global.or.b32 [%0], %1;" :: "l"(p), "r"(v) : "memory");
}
__device__ __forceinline__ void prefetch_l2(const void* p) {
    asm volatile("prefetch.global.L2 [%0];" :: "l"(p));
}
__device__ __forceinline__ void upk2(unsigned long long v, float& lo, float& hi) {
    asm("mov.b64 {%0, %1}, %2;" : "=f"(lo), "=f"(hi) : "l"(v));
}
__device__ __forceinline__ void fma2(unsigned long long& d, unsigned long long a, unsigned long long b) {
    asm("fma.rn.f32x2 %0, %1, %2, %0;" : "+l"(d) : "l"(a), "l"(b));
}
__device__ __forceinline__ float sigmoidf_(float x) { return 1.0f / (1.0f + expf(-x)); }

// Coalesced high-MLP matvec using blocked-transposed weights (solo path).
__device__ __forceinline__ float matvec_bt(const ulonglong2* __restrict__ BT2, int h,
                                           const float* __restrict__ vec_smem) {
    const ulonglong2* v = (const ulonglong2*)vec_smem;
    unsigned long long acc = 0ull;
    #pragma unroll
    for (int b = 0; b < 4; ++b) {
        ulonglong2 w[16];
        #pragma unroll
        for (int i = 0; i < 16; ++i) w[i] = BT2[(b * 16 + i) * H + h];
        #pragma unroll
        for (int i = 0; i < 16; ++i) {
            fma2(acc, w[i].x, v[b * 16 + i].x);
            fma2(acc, w[i].y, v[b * 16 + i].y);
        }
    }
    float lo, hi; upk2(acc, lo, hi);
    return lo + hi;
}

// ------------------------------- kernels -----------------------------------
// Merged clear + weight transpose. 65536 threads.
__global__ void k_prep(const float* __restrict__ Wh,  const float* __restrict__ We2n,
                       const float* __restrict__ Wre, const float* __restrict__ Wrn) {
    int idx = blockIdx.x * blockDim.x + threadIdx.x;
    if (idx < HSIZE) { g_hrow[idx] = -1; g_hcnt[idx] = 0; }
    if (idx < BDIM) g_done[idx] = 0;
    if (idx < NBATCH) g_dirty[idx] = 0;
    if (idx == 0) g_ctr = 0;
    // transpose: 4 * 64 * 256 = 65536 items
    int m = idx >> 14, rem = idx & 16383;
    int i4 = rem >> 8, h = rem & 255;
    const float* W = (m == 0) ? Wh : (m == 1) ? We2n : (m == 2) ? Wre : Wrn;
    g_BT[m][i4 * H + h] = *(const float4*)(W + (size_t)h * H + i4 * 4);
}

__global__ void k_insert(const int* __restrict__ u) {
    int idx = blockIdx.x * blockDim.x + threadIdx.x;
    if (idx >= BDIM * NSLOT) return;
    int t = idx / NSLOT, w = idx % NSLOT;
    int row = u[t * NSLOT + w];
    int prio = (w == 0) ? 16 : (w - 1);            // event applied last; later neighbor wins
    int e = (t << 10) | (prio << 5) | w;
    unsigned hsh = hashrow(row);
    for (;;) {
        int cur = atomicCAS(&g_hrow[hsh], -1, row);
        if (cur == -1 || cur == row) {
            int c = atomicAdd(&g_hcnt[hsh], 1);
            if (c < HK) g_hent[hsh][c] = e;
            break;
        }
        hsh = (hsh + 1) & HMASK;
    }
}

__global__ void k_resolve(const int* __restrict__ u, const int* __restrict__ u_neg,
                          const float* __restrict__ z0, const float* __restrict__ time_bar,
                          const float* __restrict__ td) {
    int idx = blockIdx.x * blockDim.x + threadIdx.x;
    if (idx < 1088) prefetch_l2(td + idx * 32);    // whole td array
    if (idx >= BDIM * NREAD) return;
    int t = idx / NREAD, r = idx % NREAD;
    int row = (r < NSLOT) ? u[t * NSLOT + r] : u_neg[t * NEGK + (r - NSLOT)];
    if (r >= NSLOT) prefetch_l2(time_bar + (size_t)t * NNODES + row);
    unsigned hsh = hashrow(row);
    int src = -1, bestkey = -1;
    for (;;) {
        int cur = g_hrow[hsh];
        if (cur == -1) break;
        if (cur == row) {
            int c = g_hcnt[hsh]; if (c > HK) c = HK;
            for (int i = 0; i < c; ++i) {
                int e = g_hent[hsh][i];
                if ((e >> 10) < t) {
                    int key = e >> 5;
                    if (key > bestkey) { bestkey = key; src = ((e >> 10) << 5) | (e & 31); }
                }
            }
            break;
        }
        hsh = (hsh + 1) & HMASK;
    }
    g_src[t][r] = src;
    if (src >= 0) {
        // in-batch dependency (step-slot read only) => batch must run solo
        if (r < NSLOT && ((src >> 5) >> 2) == (t >> 2)) g_dirty[t >> 2] = 1;
    } else {
        const float* p = z0 + (size_t)row * H;     // prefetch the z0 row
        #pragma unroll
        for (int l = 0; l < 8; ++l) prefetch_l2(p + l * 32);
    }
}

// Persistent main kernel: 256 threads/CTA, 2 CTAs/SM.
// ids [0,128): 4-step batches. [128,128+782): copy chunks (with winner rows
// sourced from staging). [910,1422): per-step Hawkes lambdas.
__global__ void __launch_bounds__(NTHR, 2) k_main(
    const int* __restrict__ u, const float* __restrict__ td,
    const float* __restrict__ time_bar, const float* __restrict__ time_cur,
    const int* __restrict__ u_neg, const float* __restrict__ z0,
    const float* __restrict__ bh,  const float* __restrict__ be2n,
    const float* __restrict__ bre, const float* __restrict__ brn,
    const float* __restrict__ Wt,  const float* __restrict__ bt,
    const float* __restrict__ Wom, const float* __restrict__ bom_p,
    const float* __restrict__ wt_p, const float* __restrict__ alpha_p,
    const float* __restrict__ psi_p, float* __restrict__ out)
{
    extern __shared__ float sm[];
    float* znb = sm + ZNB_OFF;     // [4][16][256]
    float* emb = sm + EMB_OFF;     // [4][256]
    float* mea = sm + MEAN_OFF;    // [4][256]
    float* tds = sm + TD_OFF;      // [4][17][4]
    int*   sint = (int*)(sm + INT_OFF);    // [0]=id, [1]=wcnt, [2..258)=wrow, [258..514)=we

    const int tid  = threadIdx.x;
    const int lane = tid & 31, wid = tid >> 5;
    float* outz = out + (BDIM + BDIM * NEGK);
    const ulonglong2* BT_h   = (const ulonglong2*)g_BT[0];
    const ulonglong2* BT_e2n = (const ulonglong2*)g_BT[1];
    const ulonglong2* BT_re  = (const ulonglong2*)g_BT[2];
    const ulonglong2* BT_rn  = (const ulonglong2*)g_BT[3];

    for (;;) {
        __syncthreads();                      // protect s_id / smem reuse
        if (tid == 0) sint[0] = atomicAdd(&g_ctr, 1);
        __syncthreads();
        const int id = sint[0];
        if (id >= TOTAL_WORK) break;

        // =================== COPY CHUNK ===================
        if (id >= NBATCH && id < NBATCH + NCHUNK) {
            int chunk = id - NBATCH;
            size_t r0 = (size_t)chunk * CPR;
            int nrow = (NNODES - (int)r0 > CPR) ? CPR : (NNODES - (int)r0);
            // find rows in this chunk that were written by some step
            if (tid == 0) sint[1] = 0;
            __syncthreads();
            if (tid < nrow) {
                int row = (int)r0 + tid;
                unsigned hsh = hashrow(row);
                for (;;) {
                    int cur = g_hrow[hsh];
                    if (cur == -1) break;
                    if (cur == row) {
                        int c = g_hcnt[hsh]; if (c > HK) c = HK;
                        int beste = -1, bestkey = -1;
                        for (int i = 0; i < c; ++i) {
                            int e = g_hent[hsh][i];
                            int key = e >> 5;
                            if (key > bestkey) { bestkey = key; beste = e; }
                        }
                        if (beste >= 0) {
                            int k = atomicAdd(&sint[1], 1);
                            sint[2 + k] = row;
                            sint[258 + k] = beste;
                        }
                        break;
                    }
                    hsh = (hsh + 1) & HMASK;
                }
            }
            __syncthreads();
            // flat streaming copy z0 -> out z_final region
            const float4* src = (const float4*)z0 + r0 * (H / 4);
            float4*       dst = (float4*)outz  + r0 * (H / 4);
            int n4 = nrow * (H / 4);
            for (int base = 0; base < n4; base += NTHR * 8) {
                float4 t[8];
                #pragma unroll
                for (int b = 0; b < 8; ++b) {
                    int i = base + tid + b * NTHR;
                    if (i < n4) t[b] = __ldcs(&src[i]);
                }
                #pragma unroll
                for (int b = 0; b < 8; ++b) {
                    int i = base + tid + b * NTHR;
                    if (i < n4) __stcs(&dst[i], t[b]);
                }
            }
            __syncthreads();
            // overwrite winner rows from their final staging version
            int wcnt = sint[1];
            for (int i = wid; i < wcnt; i += 8) {
                int row = sint[2 + i], e = sint[258 + i];
                int s = e >> 10, w = e & 31;
                int* flag = &g_done[s];
                while ((ld_acq(flag) & FULLMASK) != FULLMASK) __nanosleep(32);
                const float4* sp = (const float4*)g_staging[s][w];
                float4* dp = (float4*)outz + (size_t)row * (H / 4);
                dp[lane]      = sp[lane];
                dp[lane + 32] = sp[lane + 32];
            }
            continue;
        }

        // =================== LAMBDA POST TASK ===================
        if (id >= NBATCH + NCHUNK) {
            const int s = id - (NBATCH + NCHUNK);
            if (tid < 6) {                       // wait for lambda sources
                int r = (tid < 5) ? (NSLOT + tid) : 0;
                int sv = g_src[s][r];
                if (sv >= 0) {
                    int* flag = &g_done[sv >> 5];
                    int bit = 1 << (sv & 31);
                    while (!(ld_acq(flag) & bit)) __nanosleep(32);
                }
            }
            __syncthreads();
            const float w_t = *wt_p, alpha = *alpha_p, psi = *psi_p, bom = *bom_p;
            const float inv_psi = 1.0f / (psi + 1e-7f);
            if (wid < NEGK) {
                int node = u_neg[s * NEGK + wid];
                int sv = g_src[s][NSLOT + wid];
                const float* srcp = (sv >= 0) ? g_staging[sv >> 5][sv & 31]
                                              : (z0 + (size_t)node * H);
                float acc = 0.f;
                for (int i = lane; i < H; i += 32) acc += srcp[i] * Wom[i];
                #pragma unroll
                for (int o = 16; o; o >>= 1) acc += __shfl_down_sync(0xffffffffu, acc, o);
                if (lane == 0) {
                    float ts = time_cur[s] - time_bar[(size_t)s * NNODES + node];
                    float g = acc + bom + alpha * expf(-w_t * (ts * (1.0f / 86400.0f)));
                    float gp = fminf(fmaxf(g * inv_psi, -75.f), 75.f);
                    out[BDIM + s * NEGK + wid] = psi * log1pf(expf(gp)) * (1.0f / NEGK);
                }
            } else if (wid == 5) {
                int sv = g_src[s][0];
                const float* srcp = (sv >= 0) ? g_staging[sv >> 5][sv & 31]
                                              : (z0 + (size_t)u[s * NSLOT] * H);
                float acc = 0.f;
                for (int i = lane; i < H; i += 32) acc += srcp[i] * Wom[i];
                #pragma unroll
                for (int o = 16; o; o >>= 1) acc += __shfl_down_sync(0xffffffffu, acc, o);
                if (lane == 0) {
                    float ts = time_cur[s] - td[s * NSLOT * 4] * (1.0f / 50.0f);
                    float g = acc + bom + alpha * expf(-w_t * (ts * (1.0f / 86400.0f)));
                    float gp = fminf(fmaxf(g * inv_psi, -75.f), 75.f);
                    out[s] = psi * log1pf(expf(gp));
                }
            }
            continue;
        }

        // =================== STEP BATCH ===================
        const int s0 = id * 4;
        const int h = tid;
        const float inv_sd[4] = {1.f/50.f, 1.f/7.f, 1.f/15.f, 1.f/15.f};

        if (!g_dirty[id]) {
            // ---------- fused clean path: 4 independent steps ----------
            if (tid < 4 * NSLOT) {               // wait on external producers
                int t = s0 + tid / NSLOT, r = tid % NSLOT;
                int sv = g_src[t][r];
                if (sv >= 0) {
                    int* flag = &g_done[sv >> 5];
                    int bit = 1 << (sv & 31);
                    while (!(ld_acq(flag) & bit)) __nanosleep(32);
                }
            }
            for (int q = tid; q < 4 * NSLOT * 4; q += NTHR)   // time deltas
                tds[q] = td[s0 * NSLOT * 4 + q] * inv_sd[q & 3];
            __syncthreads();

            for (int r8 = wid; r8 < 4 * NSLOT; r8 += 8) {     // load 68 rows
                int b = r8 / NSLOT, slot = r8 % NSLOT;
                int s = s0 + b;
                int sv = g_src[s][slot];
                const float4* s4 = (sv >= 0)
                    ? (const float4*)g_staging[sv >> 5][sv & 31]
                    : (const float4*)(z0 + (size_t)u[s * NSLOT + slot] * H);
                float4* d4 = (float4*)((slot == 0) ? (emb + b * H)
                                                   : (znb + (b * DEG + slot - 1) * H));
                d4[lane]      = s4[lane];
                d4[lane + 32] = s4[lane + 32];
            }
            __syncthreads();

            #pragma unroll
            for (int b = 0; b < 4; ++b) {        // neighbor means
                float acc = 0.f;
                #pragma unroll
                for (int j = 0; j < DEG; ++j) acc += znb[(b * DEG + j) * H + tid];
                mea[b * H + tid] = acc * (1.0f / DEG);
            }
            __syncthreads();

            float4 wtr = *(const float4*)(Wt + (size_t)h * 4);
            float btv = bt[h], bhv = bh[h], brev = bre[h];
            float cb = be2n[h] + brn[h];

            // batched matvecs: weights read once for all 4 steps
            unsigned long long aE[4], aH[4], aR[4];
            #pragma unroll
            for (int b = 0; b < 4; ++b) { aE[b] = 0ull; aH[b] = 0ull; aR[b] = 0ull; }
            #pragma unroll 2
            for (int i4 = 0; i4 < H / 4; ++i4) {
                ulonglong2 wE = BT_e2n[i4 * H + h];
                ulonglong2 wH = BT_h  [i4 * H + h];
                ulonglong2 wR = BT_re [i4 * H + h];
                #pragma unroll
                for (int b = 0; b < 4; ++b) {
                    ulonglong2 e = ((const ulonglong2*)(emb + b * H))[i4];
                    ulonglong2 m = ((const ulonglong2*)(mea + b * H))[i4];
                    fma2(aE[b], wE.x, e.x); fma2(aE[b], wE.y, e.y);
                    fma2(aH[b], wH.x, m.x); fma2(aH[b], wH.y, m.y);
                    fma2(aR[b], wR.x, e.x); fma2(aR[b], wR.y, e.y);
                }
            }
            float cmn[4];
            #pragma unroll
            for (int b = 0; b < 4; ++b) {
                float l0, h0, l1, h1, l2, h2;
                upk2(aE[b], l0, h0); upk2(aH[b], l1, h1); upk2(aR[b], l2, h2);
                cmn[b] = (l0 + h0) + cb;
                const float* tb = tds + b * NSLOT * 4;
                float tf0 = btv + wtr.x*tb[0] + wtr.y*tb[1] + wtr.z*tb[2] + wtr.w*tb[3];
                g_staging[s0 + b][0][h] = sigmoidf_((l1 + h1) + bhv + (l2 + h2) + brev + tf0);
            }

            // GEMM in 2-step pairs: Wrn read once per pair
            #pragma unroll
            for (int p = 0; p < 2; ++p) {
                unsigned long long acc[2][16];
                #pragma unroll
                for (int b2 = 0; b2 < 2; ++b2)
                    #pragma unroll
                    for (int j = 0; j < 16; ++j) acc[b2][j] = 0ull;
                const float* za = znb + ((p * 2 + 0) * DEG) * H;
                const float* zb = znb + ((p * 2 + 1) * DEG) * H;
                for (int i4 = 0; i4 < H / 4; ++i4) {
                    ulonglong2 w = BT_rn[i4 * H + h];
                    #pragma unroll
                    for (int j = 0; j < 16; ++j) {
                        ulonglong2 z1 = *(const ulonglong2*)(za + j * H + i4 * 4);
                        fma2(acc[0][j], w.x, z1.x); fma2(acc[0][j], w.y, z1.y);
                        ulonglong2 z2 = *(const ulonglong2*)(zb + j * H + i4 * 4);
                        fma2(acc[1][j], w.x, z2.x); fma2(acc[1][j], w.y, z2.y);
                    }
                }
                #pragma unroll
                for (int b2 = 0; b2 < 2; ++b2) {
                    int b = p * 2 + b2, s = s0 + b;
                    const float* tb = tds + b * NSLOT * 4;
                    #pragma unroll
                    for (int j = 0; j < 16; ++j) {
                        float lo, hi; upk2(acc[b2][j], lo, hi);
                        const float* t4 = tb + (1 + j) * 4;
                        float tf = btv + wtr.x*t4[0] + wtr.y*t4[1] + wtr.z*t4[2] + wtr.w*t4[3];
                        g_staging[s][1 + j][h] = sigmoidf_(lo + hi + cmn[b] + tf);
                    }
                }
                __syncthreads();
                if (tid == 0) {
                    red_or_rel(&g_done[s0 + p * 2], FULLMASK);
                    red_or_rel(&g_done[s0 + p * 2 + 1], FULLMASK);
                }
            }
        } else {
            // ---------- dirty path: process the 4 steps sequentially ----------
            for (int b = 0; b < 4; ++b) {
                const int s = s0 + b;
                __syncthreads();
                if (tid < NSLOT) {
                    int sv = g_src[s][tid];
                    if (sv >= 0) {
                        int* flag = &g_done[sv >> 5];
                        int bit = 1 << (sv & 31);
                        while (!(ld_acq(flag) & bit)) __nanosleep(32);
                    }
                }
                if (tid >= 32 && tid < 32 + NSLOT * 4) {
                    int q = tid - 32;
                    tds[b * NSLOT * 4 + q] = td[(s * NSLOT) * 4 + q] * inv_sd[q & 3];
                }
                __syncthreads();
                for (int r = wid; r < NSLOT; r += 8) {
                    int sv = g_src[s][r];
                    const float4* s4 = (sv >= 0)
                        ? (const float4*)g_staging[sv >> 5][sv & 31]
                        : (const float4*)(z0 + (size_t)u[s * NSLOT + r] * H);
                    float4* d4 = (float4*)((r == 0) ? (emb + b * H)
                                                    : (znb + (b * DEG + r - 1) * H));
                    d4[lane]      = s4[lane];
                    d4[lane + 32] = s4[lane + 32];
                }
                __syncthreads();
                {
                    float acc = 0.f;
                    #pragma unroll
                    for (int j = 0; j < DEG; ++j) acc += znb[(b * DEG + j) * H + tid];
                    mea[b * H + tid] = acc * (1.0f / DEG);
                }
                __syncthreads();

                float4 wtr = *(const float4*)(Wt + (size_t)h * 4);
                float btv = bt[h];
                const float* tb = tds + b * NSLOT * 4;

                float cmn = matvec_bt(BT_e2n, h, emb + b * H) + be2n[h] + brn[h];
                float ah = matvec_bt(BT_h,  h, mea + b * H);
                float ae = matvec_bt(BT_re, h, emb + b * H);
                float tf0 = btv + wtr.x*tb[0] + wtr.y*tb[1] + wtr.z*tb[2] + wtr.w*tb[3];
                g_staging[s][0][h] = sigmoidf_(ah + bh[h] + ae + bre[h] + tf0);

                unsigned long long acc2[DEG];
                #pragma unroll
                for (int j = 0; j < DEG; ++j) acc2[j] = 0ull;
                const float* zz = znb + (b * DEG) * H;
                for (int i4 = 0; i4 < H / 4; ++i4) {
                    ulonglong2 w = BT_rn[i4 * H + h];
                    #pragma unroll
                    for (int j = 0; j < DEG; ++j) {
                        ulonglong2 z = *(const ulonglong2*)(zz + j * H + i4 * 4);
                        fma2(acc2[j], w.x, z.x); fma2(acc2[j], w.y, z.y);
                    }
                }
                #pragma unroll
                for (int j = 0; j < DEG; ++j) {
                    float lo, hi; upk2(acc2[j], lo, hi);
                    const float* t4 = tb + (1 + j) * 4;
                    float tf = btv + wtr.x*t4[0] + wtr.y*t4[1] + wtr.z*t4[2] + wtr.w*t4[3];
                    g_staging[s][1 + j][h] = sigmoidf_(lo + hi + cmn + tf);
                }
                __syncthreads();
                if (tid == 0) red_or_rel(&g_done[s], FULLMASK);
            }
        }
    }
}

// ------------------------------- launch ------------------------------------
extern "C" void kernel_launch(void* const* d_in, const int* in_sizes, int n_in,
                              void* d_out, int out_size) {
    const int*   u     = (const int*)  d_in[0];
    const float* td    = (const float*)d_in[1];
    const float* tbar  = (const float*)d_in[2];
    const float* tcur  = (const float*)d_in[3];
    // d_in[4] significance, d_in[5] magnitudo: unused by reference
    const int*   uneg  = (const int*)  d_in[6];
    const float* z0    = (const float*)d_in[7];
    const float* Wh    = (const float*)d_in[8];
    const float* bh    = (const float*)d_in[9];
    const float* We2n  = (const float*)d_in[10];
    const float* be2n  = (const float*)d_in[11];
    const float* Wre   = (const float*)d_in[12];
    const float* bre   = (const float*)d_in[13];
    const float* Wrn   = (const float*)d_in[14];
    const float* brn   = (const float*)d_in[15];
    const float* Wt    = (const float*)d_in[16];
    const float* bt    = (const float*)d_in[17];
    const float* Wom   = (const float*)d_in[18];
    const float* bom   = (const float*)d_in[19];
    const float* wt    = (const float*)d_in[20];
    const float* alpha = (const float*)d_in[21];
    const float* psi   = (const float*)d_in[22];
    float* out = (float*)d_out;

    static int smem_set = 0;
    if (!smem_set) {
        cudaFuncSetAttribute(k_main, cudaFuncAttributeMaxDynamicSharedMemorySize, SMEM_BYTES);
        smem_set = 1;
    }

    k_prep   <<<256, 256>>>(Wh, We2n, Wre, Wrn);
    k_insert <<<(BDIM * NSLOT + 255) / 256, 256>>>(u);
    k_resolve<<<(BDIM * NREAD + 255) / 256, 256>>>(u, uneg, z0, tbar, td);

    int dev = 0, nsm = 148;
    cudaGetDevice(&dev);
    cudaDeviceGetAttribute(&nsm, cudaDevAttrMultiProcessorCount, dev);

    k_main<<<nsm * 2, NTHR, SMEM_BYTES>>>(u, td, tbar, tcur, uneg, z0,
                                          bh, be2n, bre, brn, Wt, bt,
                                          Wom, bom, wt, alpha, psi, out);
}

// round 10
// speedup vs baseline: 1.9473x; 1.9473x over previous
#include <cuda_runtime.h>
#include <math.h>

// Problem constants (fixed shapes per reference)
#define BDIM    512
#define DEG     16
#define NSLOT   17
#define NREAD   22
#define NEGK    5
#define H       256
#define NNODES  200000
#define HBITS   15
#define HSIZE   (1 << HBITS)
#define HMASK   (HSIZE - 1)
#define HK      16
#define CPR     256
#define NCHUNK  ((NNODES + CPR - 1) / CPR)     // 782
#define NBATCH  (BDIM / 4)                     // 128 step-batches
#define TOTAL_WORK (NBATCH + NCHUNK)           // 910: batches then copies
#define NTHR    256
#define FULLMASK 0x1FFFF

// ------------------------- persistent device state -------------------------
__device__ __align__(16) float g_staging[BDIM][NSLOT][H];   // 8.9 MB
// Blocked-transposed weights: g_BT[m][i4*H + h] = float4(W_m[h][4*i4..])
// m: 0=Wh, 1=We2n, 2=Wre, 3=Wrn
__device__ __align__(16) float4 g_BT[4][(H / 4) * H];       // 1 MB
__device__ int g_done[BDIM];           // bitmask of completed slots
__device__ int g_needed[BDIM];         // slots some future step reads
__device__ int g_dirty[NBATCH];        // batch has in-batch dependency
__device__ int g_src[BDIM][NREAD];     // -1 => z0[row], else (t'<<5)|w'
__device__ int g_ctr;
__device__ int g_hrow[HSIZE];
__device__ int g_hcnt[HSIZE];
__device__ int g_hent[HSIZE][HK];      // e = (t<<10)|(prio<<5)|w

// ------------------------------- helpers -----------------------------------
__device__ __forceinline__ unsigned hashrow(int row) {
    return ((unsigned)row * 2654435761u) >> (32 - HBITS);
}
__device__ __forceinline__ int ld_acq(const int* p) {
    int v; asm volatile("ld.acquire.gpu.b32 %0, [%1];" : "=r"(v) : "l"(p) : "memory"); return v;
}
__device__ __forceinline__ void red_or_rel(int* p, int v) {
    asm volatile("red.release.gpu.global.or.b32 [%0], %1;" :: "l"(p), "r"(v) : "memory");
}
__device__ __forceinline__ void prefetch_l2(const void* p) {
    asm volatile("prefetch.global.L2 [%0];" :: "l"(p));
}
__device__ __forceinline__ void upk2(unsigned long long v, float& lo, float& hi) {
    asm("mov.b64 {%0, %1}, %2;" : "=f"(lo), "=f"(hi) : "l"(v));
}
__device__ __forceinline__ void fma2(unsigned long long& d, unsigned long long a, unsigned long long b) {
    asm("fma.rn.f32x2 %0, %1, %2, %0;" : "+l"(d) : "l"(a), "l"(b));
}
__device__ __forceinline__ float sigmoidf_(float x) { return 1.0f / (1.0f + expf(-x)); }

// Coalesced matvec via blocked-transposed weights; vec may be smem or gmem.
__device__ __forceinline__ float matvec_bt(const ulonglong2* __restrict__ BT2, int h,
                                           const float* __restrict__ vec) {
    const ulonglong2* v = (const ulonglong2*)vec;
    unsigned long long acc = 0ull;
    #pragma unroll
    for (int b = 0; b < 4; ++b) {
        ulonglong2 w[16];
        #pragma unroll
        for (int i = 0; i < 16; ++i) w[i] = BT2[(b * 16 + i) * H + h];
        #pragma unroll
        for (int i = 0; i < 16; ++i) {
            fma2(acc, w[i].x, v[b * 16 + i].x);
            fma2(acc, w[i].y, v[b * 16 + i].y);
        }
    }
    float lo, hi; upk2(acc, lo, hi);
    return lo + hi;
}

// ------------------------------- kernels -----------------------------------
// Merged clear + weight transpose. 65536 threads.
__global__ void k_prep(const float* __restrict__ Wh,  const float* __restrict__ We2n,
                       const float* __restrict__ Wre, const float* __restrict__ Wrn) {
    int idx = blockIdx.x * blockDim.x + threadIdx.x;
    if (idx < HSIZE) { g_hrow[idx] = -1; g_hcnt[idx] = 0; }
    if (idx < BDIM) { g_done[idx] = 0; g_needed[idx] = 0; }
    if (idx < NBATCH) g_dirty[idx] = 0;
    if (idx == 0) g_ctr = 0;
    int m = idx >> 14, rem = idx & 16383;
    int i4 = rem >> 8, h = rem & 255;
    const float* W = (m == 0) ? Wh : (m == 1) ? We2n : (m == 2) ? Wre : Wrn;
    g_BT[m][i4 * H + h] = *(const float4*)(W + (size_t)h * H + i4 * 4);
}

__global__ void k_insert(const int* __restrict__ u) {
    int idx = blockIdx.x * blockDim.x + threadIdx.x;
    if (idx >= BDIM * NSLOT) return;
    int t = idx / NSLOT, w = idx % NSLOT;
    int row = u[t * NSLOT + w];
    int prio = (w == 0) ? 16 : (w - 1);            // event applied last; later neighbor wins
    int e = (t << 10) | (prio << 5) | w;
    unsigned hsh = hashrow(row);
    for (;;) {
        int cur = atomicCAS(&g_hrow[hsh], -1, row);
        if (cur == -1 || cur == row) {
            int c = atomicAdd(&g_hcnt[hsh], 1);
            if (c < HK) g_hent[hsh][c] = e;
            break;
        }
        hsh = (hsh + 1) & HMASK;
    }
}

__global__ void k_resolve(const int* __restrict__ u, const int* __restrict__ u_neg,
                          const float* __restrict__ z0, const float* __restrict__ time_bar,
                          const float* __restrict__ td) {
    int idx = blockIdx.x * blockDim.x + threadIdx.x;
    if (idx < 1088) prefetch_l2(td + idx * 32);    // whole td array
    if (idx >= BDIM * NREAD) return;
    int t = idx / NREAD, r = idx % NREAD;
    int row = (r < NSLOT) ? u[t * NSLOT + r] : u_neg[t * NEGK + (r - NSLOT)];
    if (r >= NSLOT) prefetch_l2(time_bar + (size_t)t * NNODES + row);
    unsigned hsh = hashrow(row);
    int src = -1, bestkey = -1;
    for (;;) {
        int cur = g_hrow[hsh];
        if (cur == -1) break;
        if (cur == row) {
            int c = g_hcnt[hsh]; if (c > HK) c = HK;
            for (int i = 0; i < c; ++i) {
                int e = g_hent[hsh][i];
                if ((e >> 10) < t) {
                    int key = e >> 5;
                    if (key > bestkey) { bestkey = key; src = ((e >> 10) << 5) | (e & 31); }
                }
            }
            break;
        }
        hsh = (hsh + 1) & HMASK;
    }
    g_src[t][r] = src;
    if (src >= 0) {
        if (r < NSLOT) {
            atomicOr(&g_needed[src >> 5], 1 << (src & 31));
            if (((src >> 5) >> 2) == (t >> 2)) g_dirty[t >> 2] = 1;  // in-batch dep
        }
    } else {
        const float* p = z0 + (size_t)row * H;     // prefetch the z0 row
        #pragma unroll
        for (int l = 0; l < 8; ++l) prefetch_l2(p + l * 32);
    }
}

// Persistent main kernel: 256 threads/CTA, 2 CTAs/SM.
// ids [0,128): 4-step batches (claimed by first CTAs at t=0).
// ids [128,910): plain z0->out copy chunks (claimed by the remaining CTAs at t=0).
__global__ void __launch_bounds__(NTHR, 2) k_main(
    const int* __restrict__ u, const float* __restrict__ td,
    const float* __restrict__ z0,
    const float* __restrict__ bh,  const float* __restrict__ be2n,
    const float* __restrict__ bre, const float* __restrict__ brn,
    const float* __restrict__ Wt,  const float* __restrict__ bt,
    float* __restrict__ out)
{
    __shared__ __align__(16) float s_znb[DEG][H];        // 16KB: one step's neighbors
    __shared__ __align__(16) float s_emb[4][H];          // 4KB
    __shared__ __align__(16) float s_mean[4][H];         // 4KB
    __shared__ float s_tds[4][NSLOT][4];
    __shared__ unsigned long long s_ptr[4][NSLOT];       // resolved row pointers
    __shared__ int s_need[4];
    __shared__ int s_id;

    const int tid  = threadIdx.x;              // == h (output column)
    const int lane = tid & 31, wid = tid >> 5;
    float* outz = out + (BDIM + BDIM * NEGK);
    const ulonglong2* BT_h   = (const ulonglong2*)g_BT[0];
    const ulonglong2* BT_e2n = (const ulonglong2*)g_BT[1];
    const ulonglong2* BT_re  = (const ulonglong2*)g_BT[2];
    const ulonglong2* BT_rn  = (const ulonglong2*)g_BT[3];
    const float inv_sd[4] = {1.f/50.f, 1.f/7.f, 1.f/15.f, 1.f/15.f};
    const int h = tid;

    for (;;) {
        __syncthreads();                      // protect s_id / smem reuse
        if (tid == 0) s_id = atomicAdd(&g_ctr, 1);
        __syncthreads();
        const int id = s_id;
        if (id >= TOTAL_WORK) break;

        // =================== COPY CHUNK (no waits, pure bandwidth) ===================
        if (id >= NBATCH) {
            int chunk = id - NBATCH;
            size_t r0 = (size_t)chunk * CPR;
            int nrow = (NNODES - (int)r0 > CPR) ? CPR : (NNODES - (int)r0);
            const float4* src = (const float4*)z0 + r0 * (H / 4);
            float4*       dst = (float4*)outz  + r0 * (H / 4);
            int n4 = nrow * (H / 4);
            for (int base = 0; base < n4; base += NTHR * 8) {
                float4 t[8];
                #pragma unroll
                for (int b = 0; b < 8; ++b) {
                    int i = base + tid + b * NTHR;
                    if (i < n4) t[b] = __ldcs(&src[i]);
                }
                #pragma unroll
                for (int b = 0; b < 8; ++b) {
                    int i = base + tid + b * NTHR;
                    if (i < n4) __stcs(&dst[i], t[b]);
                }
            }
            continue;
        }

        // =================== STEP BATCH ===================
        const int s0 = id * 4;

        if (g_dirty[id]) {
            // ---------- dirty path: 4 steps sequentially (R8-style solo) ----------
            for (int b = 0; b < 4; ++b) {
                const int s = s0 + b;
                __syncthreads();
                if (tid < NSLOT) {                       // wait + resolve pointer
                    int sv = g_src[s][tid];
                    const float* p;
                    if (sv >= 0) {
                        int* flag = &g_done[sv >> 5];
                        int bit = 1 << (sv & 31);
                        while (!(ld_acq(flag) & bit)) __nanosleep(32);
                        p = g_staging[sv >> 5][sv & 31];
                    } else {
                        p = z0 + (size_t)u[s * NSLOT + tid] * H;
                    }
                    s_ptr[0][tid] = (unsigned long long)p;
                }
                if (tid >= 32 && tid < 32 + NSLOT * 4) {
                    int q = tid - 32;
                    s_tds[0][q >> 2][q & 3] = td[(s * NSLOT) * 4 + q] * inv_sd[q & 3];
                }
                __syncthreads();
                for (int r = wid; r < NSLOT; r += 8) {
                    const float4* s4 = (const float4*)s_ptr[0][r];
                    float4* d4 = (r == 0) ? (float4*)s_emb[0] : (float4*)s_znb[r - 1];
                    d4[lane]      = s4[lane];
                    d4[lane + 32] = s4[lane + 32];
                }
                __syncthreads();
                {
                    float acc = 0.f;
                    #pragma unroll
                    for (int j = 0; j < DEG; ++j) acc += s_znb[j][tid];
                    s_mean[0][tid] = acc * (1.0f / DEG);
                }
                __syncthreads();

                float4 wtr = *(const float4*)(Wt + (size_t)h * 4);
                float btv = bt[h];
                const float* tb = &s_tds[0][0][0];

                float cmn = matvec_bt(BT_e2n, h, s_emb[0]) + be2n[h] + brn[h];
                float ah = matvec_bt(BT_h,  h, s_mean[0]);
                float ae = matvec_bt(BT_re, h, s_emb[0]);
                float tf0 = btv + wtr.x*tb[0] + wtr.y*tb[1] + wtr.z*tb[2] + wtr.w*tb[3];
                g_staging[s][0][h] = sigmoidf_(ah + bh[h] + ae + bre[h] + tf0);

                unsigned long long acc2[DEG];
                #pragma unroll
                for (int j = 0; j < DEG; ++j) acc2[j] = 0ull;
                for (int i4 = 0; i4 < H / 4; ++i4) {
                    ulonglong2 w = BT_rn[i4 * H + h];
                    #pragma unroll
                    for (int j = 0; j < DEG; ++j) {
                        ulonglong2 z = *(const ulonglong2*)&s_znb[j][i4 * 4];
                        fma2(acc2[j], w.x, z.x); fma2(acc2[j], w.y, z.y);
                    }
                }
                #pragma unroll
                for (int j = 0; j < DEG; ++j) {
                    float lo, hi; upk2(acc2[j], lo, hi);
                    const float* t4 = tb + (1 + j) * 4;
                    float tf = btv + wtr.x*t4[0] + wtr.y*t4[1] + wtr.z*t4[2] + wtr.w*t4[3];
                    g_staging[s][1 + j][h] = sigmoidf_(lo + hi + cmn + tf);
                }
                __syncthreads();
                if (tid == 0) red_or_rel(&g_done[s], FULLMASK);
            }
            continue;
        }

        // ---------- fused clean path: 4 independent steps ----------
        // Phase A: wait on external producers; resolve row pointers
        if (tid < 4 * NSLOT) {
            int t = s0 + tid / NSLOT, r = tid % NSLOT;
            int sv = g_src[t][r];
            const float* p;
            if (sv >= 0) {
                int* flag = &g_done[sv >> 5];
                int bit = 1 << (sv & 31);
                while (!(ld_acq(flag) & bit)) __nanosleep(32);
                p = g_staging[sv >> 5][sv & 31];
            } else {
                p = z0 + (size_t)u[t * NSLOT + r] * H;
            }
            s_ptr[tid / NSLOT][r] = (unsigned long long)p;
        } else if (tid >= 96 && tid < 100) {
            s_need[tid - 96] = g_needed[s0 + tid - 96];
        }
        for (int q = tid; q < 4 * NSLOT * 4; q += NTHR)
            ((float*)s_tds)[q] = td[s0 * NSLOT * 4 + q] * inv_sd[q & 3];
        __syncthreads();

        // emb rows: 8 warps, 2 per row
        {
            int b = wid >> 1, half = wid & 1;
            const float4* s4 = (const float4*)s_ptr[b][0];
            float4* d4 = (float4*)s_emb[b];
            d4[half * 32 + lane] = s4[half * 32 + lane];
        }
        // means from global/L2 rows (coalesced; rows re-read in Phase C from smem)
        {
            #pragma unroll
            for (int b = 0; b < 4; ++b) {
                float acc = 0.f;
                #pragma unroll
                for (int j = 0; j < DEG; ++j)
                    acc += ((const float*)s_ptr[b][1 + j])[tid];
                s_mean[b][tid] = acc * (1.0f / DEG);
            }
        }
        __syncthreads();

        float4 wtr = *(const float4*)(Wt + (size_t)h * 4);
        float btv = bt[h], bhv = bh[h], brev = bre[h];
        float cb = be2n[h] + brn[h];

        // Phase B: batched matvecs — weights read ONCE for all 4 steps
        unsigned long long aE[4], aH[4], aR[4];
        #pragma unroll
        for (int b = 0; b < 4; ++b) { aE[b] = 0ull; aH[b] = 0ull; aR[b] = 0ull; }
        for (int i4 = 0; i4 < H / 4; ++i4) {
            ulonglong2 wE = BT_e2n[i4 * H + h];
            ulonglong2 wH = BT_h  [i4 * H + h];
            ulonglong2 wR = BT_re [i4 * H + h];
            #pragma unroll
            for (int b = 0; b < 4; ++b) {
                ulonglong2 e = ((const ulonglong2*)s_emb[b])[i4];
                ulonglong2 m = ((const ulonglong2*)s_mean[b])[i4];
                fma2(aE[b], wE.x, e.x); fma2(aE[b], wE.y, e.y);
                fma2(aH[b], wH.x, m.x); fma2(aH[b], wH.y, m.y);
                fma2(aR[b], wR.x, e.x); fma2(aR[b], wR.y, e.y);
            }
        }
        float cmn[4];
        #pragma unroll
        for (int b = 0; b < 4; ++b) {
            float l0, h0, l1, h1, l2, h2;
            upk2(aE[b], l0, h0); upk2(aH[b], l1, h1); upk2(aR[b], l2, h2);
            cmn[b] = (l0 + h0) + cb;
            const float* tb = &s_tds[b][0][0];
            float tf0 = btv + wtr.x*tb[0] + wtr.y*tb[1] + wtr.z*tb[2] + wtr.w*tb[3];
            g_staging[s0 + b][0][h] = sigmoidf_((l1 + h1) + bhv + (l2 + h2) + brev + tf0);
        }
        __syncthreads();
        if (tid == 0) {
            #pragma unroll
            for (int b = 0; b < 4; ++b) red_or_rel(&g_done[s0 + b], 1);   // z_ev early
        }

        // Phase B2: publish needed neighbor slots early (vec from global row)
        {
            bool any = false;
            #pragma unroll
            for (int b = 0; b < 4; ++b) {
                for (int m = (s_need[b] >> 1) & 0xFFFF; m; m &= (m - 1)) {
                    int j = __ffs(m) - 1;
                    float d = matvec_bt(BT_rn, h, (const float*)s_ptr[b][1 + j]);
                    const float* t4 = &s_tds[b][1 + j][0];
                    float tf = btv + wtr.x*t4[0] + wtr.y*t4[1] + wtr.z*t4[2] + wtr.w*t4[3];
                    g_staging[s0 + b][1 + j][h] = sigmoidf_(d + cmn[b] + tf);
                    any = true;
                }
            }
            if (any) {
                __syncthreads();
                if (tid == 0) {
                    #pragma unroll
                    for (int b = 0; b < 4; ++b)
                        if (s_need[b] >> 1) red_or_rel(&g_done[s0 + b], s_need[b] & ~1);
                }
            }
        }

        // Phase C: per-step solo GEMM (register-safe: 16 accumulators)
        for (int b = 0; b < 4; ++b) {
            const int s = s0 + b;
            __syncthreads();                 // protect s_znb reuse
            for (int r = wid; r < DEG; r += 8) {
                const float4* s4 = (const float4*)s_ptr[b][1 + r];
                float4* d4 = (float4*)s_znb[r];
                d4[lane]      = s4[lane];
                d4[lane + 32] = s4[lane + 32];
            }
            __syncthreads();
            unsigned long long acc2[DEG];
            #pragma unroll
            for (int j = 0; j < DEG; ++j) acc2[j] = 0ull;
            for (int i4 = 0; i4 < H / 4; ++i4) {
                ulonglong2 w = BT_rn[i4 * H + h];
                #pragma unroll
                for (int j = 0; j < DEG; ++j) {
                    ulonglong2 z = *(const ulonglong2*)&s_znb[j][i4 * 4];
                    fma2(acc2[j], w.x, z.x); fma2(acc2[j], w.y, z.y);
                }
            }
            const float* tb = &s_tds[b][0][0];
            #pragma unroll
            for (int j = 0; j < DEG; ++j) {
                float lo, hi; upk2(acc2[j], lo, hi);
                const float* t4 = tb + (1 + j) * 4;
                float tf = btv + wtr.x*t4[0] + wtr.y*t4[1] + wtr.z*t4[2] + wtr.w*t4[3];
                g_staging[s][1 + j][h] = sigmoidf_(lo + hi + cmn[b] + tf);
            }
            __syncthreads();
            if (tid == 0) red_or_rel(&g_done[s], FULLMASK);
        }
    }
}

// Post pass: one block per step. Hawkes lambdas (pos + 5 neg) and final scatter
// of last-writer rows over the copied z0 region. Runs after k_main completes.
__global__ void __launch_bounds__(NTHR) k_post(
    const int* __restrict__ u, const int* __restrict__ u_neg,
    const float* __restrict__ time_bar, const float* __restrict__ time_cur,
    const float* __restrict__ td, const float* __restrict__ z0,
    const float* __restrict__ Wom, const float* __restrict__ bom_p,
    const float* __restrict__ wt_p, const float* __restrict__ alpha_p,
    const float* __restrict__ psi_p, float* __restrict__ out)
{
    const int s = blockIdx.x;
    const int tid = threadIdx.x, lane = tid & 31, wid = tid >> 5;
    const float w_t = *wt_p, alpha = *alpha_p, psi = *psi_p, bom = *bom_p;
    const float inv_psi = 1.0f / (psi + 1e-7f);
    float* outz = out + (BDIM + BDIM * NEGK);

    if (wid < NEGK) {                            // negative lambdas
        int node = u_neg[s * NEGK + wid];
        int sv = g_src[s][NSLOT + wid];
        const float* srcp = (sv >= 0) ? g_staging[sv >> 5][sv & 31]
                                      : (z0 + (size_t)node * H);
        float acc = 0.f;
        for (int i = lane; i < H; i += 32) acc += srcp[i] * Wom[i];
        #pragma unroll
        for (int o = 16; o; o >>= 1) acc += __shfl_down_sync(0xffffffffu, acc, o);
        if (lane == 0) {
            float ts = time_cur[s] - time_bar[(size_t)s * NNODES + node];
            float g = acc + bom + alpha * expf(-w_t * (ts * (1.0f / 86400.0f)));
            float gp = fminf(fmaxf(g * inv_psi, -75.f), 75.f);
            out[BDIM + s * NEGK + wid] = psi * log1pf(expf(gp)) * (1.0f / NEGK);
        }
    } else if (wid == 5) {                       // positive lambda
        int sv = g_src[s][0];
        const float* srcp = (sv >= 0) ? g_staging[sv >> 5][sv & 31]
                                      : (z0 + (size_t)u[s * NSLOT] * H);
        float acc = 0.f;
        for (int i = lane; i < H; i += 32) acc += srcp[i] * Wom[i];
        #pragma unroll
        for (int o = 16; o; o >>= 1) acc += __shfl_down_sync(0xffffffffu, acc, o);
        if (lane == 0) {
            float ts = time_cur[s] - td[s * NSLOT * 4] * (1.0f / 50.0f);
            float g = acc + bom + alpha * expf(-w_t * (ts * (1.0f / 86400.0f)));
            float gp = fminf(fmaxf(g * inv_psi, -75.f), 75.f);
            out[s] = psi * log1pf(expf(gp));
        }
    }

    // scatter: warp handles slots wid, wid+8, wid+16
    for (int w = wid; w < NSLOT; w += 8) {
        int row = u[s * NSLOT + w];
        unsigned hsh = hashrow(row);
        int beste = -1, bestkey = -1;
        for (;;) {
            int cur = g_hrow[hsh];
            if (cur == -1) break;
            if (cur == row) {
                int c = g_hcnt[hsh]; if (c > HK) c = HK;
                for (int i = 0; i < c; ++i) {
                    int e = g_hent[hsh][i];
                    int key = e >> 5;
                    if (key > bestkey) { bestkey = key; beste = e; }
                }
                break;
            }
            hsh = (hsh + 1) & HMASK;
        }
        int prio = (w == 0) ? 16 : (w - 1);
        if (beste == ((s << 10) | (prio << 5) | w)) {   // this (s,w) is the last writer
            const float4* src = (const float4*)g_staging[s][w];
            float4* dst = (float4*)outz + (size_t)row * (H / 4);
            dst[lane]      = src[lane];
            dst[lane + 32] = src[lane + 32];
        }
    }
}

// ------------------------------- launch ------------------------------------
extern "C" void kernel_launch(void* const* d_in, const int* in_sizes, int n_in,
                              void* d_out, int out_size) {
    const int*   u     = (const int*)  d_in[0];
    const float* td    = (const float*)d_in[1];
    const float* tbar  = (const float*)d_in[2];
    const float* tcur  = (const float*)d_in[3];
    // d_in[4] significance, d_in[5] magnitudo: unused by reference
    const int*   uneg  = (const int*)  d_in[6];
    const float* z0    = (const float*)d_in[7];
    const float* Wh    = (const float*)d_in[8];
    const float* bh    = (const float*)d_in[9];
    const float* We2n  = (const float*)d_in[10];
    const float* be2n  = (const float*)d_in[11];
    const float* Wre   = (const float*)d_in[12];
    const float* bre   = (const float*)d_in[13];
    const float* Wrn   = (const float*)d_in[14];
    const float* brn   = (const float*)d_in[15];
    const float* Wt    = (const float*)d_in[16];
    const float* bt    = (const float*)d_in[17];
    const float* Wom   = (const float*)d_in[18];
    const float* bom   = (const float*)d_in[19];
    const float* wt    = (const float*)d_in[20];
    const float* alpha = (const float*)d_in[21];
    const float* psi   = (const float*)d_in[22];
    float* out = (float*)d_out;

    k_prep   <<<256, 256>>>(Wh, We2n, Wre, Wrn);
    k_insert <<<(BDIM * NSLOT + 255) / 256, 256>>>(u);
    k_resolve<<<(BDIM * NREAD + 255) / 256, 256>>>(u, uneg, z0, tbar, td);

    int dev = 0, nsm = 148;
    cudaGetDevice(&dev);
    cudaDeviceGetAttribute(&nsm, cudaDevAttrMultiProcessorCount, dev);

    k_main<<<nsm * 2, NTHR>>>(u, td, z0, bh, be2n, bre, brn, Wt, bt, out);

    k_post<<<BDIM, NTHR>>>(u, uneg, tbar, tcur, td, z0,
                           Wom, bom, wt, alpha, psi, out);
}

// round 11
// speedup vs baseline: 3.5611x; 1.8288x over previous
#include <cuda_runtime.h>
#include <math.h>

// Problem constants (fixed shapes per reference)
#define BDIM    512
#define DEG     16
#define NSLOT   17
#define NREAD   22
#define NEGK    5
#define H       256
#define NNODES  200000
#define HBITS   15
#define HSIZE   (1 << HBITS)
#define HMASK   (HSIZE - 1)
#define HK      16
#define CPR     256
#define NCHUNK  ((NNODES + CPR - 1) / CPR)     // 782
#define TOTAL_WORK (BDIM + NCHUNK)             // steps first, then copies
#define NTHR    256
#define FULLMASK 0x1FFFF
#define TILE    32768                           // TMA copy tile (bytes)
#define DSMEM   (2 * TILE)                      // two tile buffers

// ------------------------- persistent device state -------------------------
__device__ __align__(16) float g_staging[BDIM][NSLOT][H];   // 8.9 MB
// Blocked-transposed weights: g_BT[m][i4*H + h] = float4(W_m[h][4*i4..])
// m: 0=Wh, 1=We2n, 2=Wre, 3=Wrn
__device__ __align__(16) float4 g_BT[4][(H / 4) * H];       // 1 MB
__device__ int g_done[BDIM];           // bitmask of completed slots
__device__ int g_needed[BDIM];         // slots some future step reads
__device__ int g_src[BDIM][NREAD];     // -1 => z0[row], else (t'<<5)|w'
__device__ int g_ctr;
__device__ int g_hrow[HSIZE];
__device__ int g_hcnt[HSIZE];
__device__ int g_hent[HSIZE][HK];      // e = (t<<10)|(prio<<5)|w

// ------------------------------- helpers -----------------------------------
__device__ __forceinline__ unsigned hashrow(int row) {
    return ((unsigned)row * 2654435761u) >> (32 - HBITS);
}
__device__ __forceinline__ int ld_acq(const int* p) {
    int v; asm volatile("ld.acquire.gpu.b32 %0, [%1];" : "=r"(v) : "l"(p) : "memory"); return v;
}
__device__ __forceinline__ void red_or_rel(int* p, int v) {
    asm volatile("red.release.gpu.global.or.b32 [%0], %1;" :: "l"(p), "r"(v) : "memory");
}
__device__ __forceinline__ void prefetch_l2(const void* p) {
    asm volatile("prefetch.global.L2 [%0];" :: "l"(p));
}
__device__ __forceinline__ void upk2(unsigned long long v, float& lo, float& hi) {
    asm("mov.b64 {%0, %1}, %2;" : "=f"(lo), "=f"(hi) : "l"(v));
}
__device__ __forceinline__ void fma2(unsigned long long& d, unsigned long long a, unsigned long long b) {
    asm("fma.rn.f32x2 %0, %1, %2, %0;" : "+l"(d) : "l"(a), "l"(b));
}
__device__ __forceinline__ float sigmoidf_(float x) { return 1.0f / (1.0f + expf(-x)); }

// ---- TMA bulk copy primitives ----
__device__ __forceinline__ void mbar_init(unsigned a, unsigned cnt) {
    asm volatile("mbarrier.init.shared.b64 [%0], %1;" :: "r"(a), "r"(cnt) : "memory");
}
__device__ __forceinline__ void mbar_expect(unsigned a, unsigned bytes) {
    asm volatile("mbarrier.arrive.expect_tx.shared.b64 _, [%0], %1;" :: "r"(a), "r"(bytes) : "memory");
}
__device__ __forceinline__ void mbar_wait(unsigned a, unsigned ph) {
    asm volatile(
        "{\n\t.reg .pred P;\n\t"
        "W%=:\n\t"
        "mbarrier.try_wait.parity.shared.b64 P, [%0], %1;\n\t"
        "@!P bra W%=;\n\t}"
        :: "r"(a), "r"(ph) : "memory");
}
__device__ __forceinline__ void bulk_g2s(unsigned saddr, const void* g, unsigned bytes, unsigned mbar) {
    asm volatile("cp.async.bulk.shared::cta.global.mbarrier::complete_tx::bytes [%0], [%1], %2, [%3];"
        :: "r"(saddr), "l"(g), "r"(bytes), "r"(mbar) : "memory");
}
__device__ __forceinline__ void bulk_s2g(void* g, unsigned saddr, unsigned bytes) {
    asm volatile("cp.async.bulk.global.shared::cta.bulk_group [%0], [%1], %2;"
        :: "l"(g), "r"(saddr), "r"(bytes) : "memory");
}

// Coalesced matvec via blocked-transposed weights; vec from smem.
__device__ __forceinline__ float matvec_bt(const ulonglong2* __restrict__ BT2, int h,
                                           const float* __restrict__ vec) {
    const ulonglong2* v = (const ulonglong2*)vec;
    unsigned long long acc = 0ull;
    #pragma unroll
    for (int b = 0; b < 4; ++b) {
        ulonglong2 w[16];
        #pragma unroll
        for (int i = 0; i < 16; ++i) w[i] = BT2[(b * 16 + i) * H + h];
        #pragma unroll
        for (int i = 0; i < 16; ++i) {
            fma2(acc, w[i].x, v[b * 16 + i].x);
            fma2(acc, w[i].y, v[b * 16 + i].y);
        }
    }
    float lo, hi; upk2(acc, lo, hi);
    return lo + hi;
}

// ------------------------------- kernels -----------------------------------
// Merged clear + weight transpose. 65536 threads.
__global__ void k_prep(const float* __restrict__ Wh,  const float* __restrict__ We2n,
                       const float* __restrict__ Wre, const float* __restrict__ Wrn) {
    int idx = blockIdx.x * blockDim.x + threadIdx.x;
    if (idx < HSIZE) { g_hrow[idx] = -1; g_hcnt[idx] = 0; }
    if (idx < BDIM) { g_done[idx] = 0; g_needed[idx] = 0; }
    if (idx == 0) g_ctr = 0;
    int m = idx >> 14, rem = idx & 16383;
    int i4 = rem >> 8, h = rem & 255;
    const float* W = (m == 0) ? Wh : (m == 1) ? We2n : (m == 2) ? Wre : Wrn;
    g_BT[m][i4 * H + h] = *(const float4*)(W + (size_t)h * H + i4 * 4);
}

__global__ void k_insert(const int* __restrict__ u) {
    int idx = blockIdx.x * blockDim.x + threadIdx.x;
    if (idx >= BDIM * NSLOT) return;
    int t = idx / NSLOT, w = idx % NSLOT;
    int row = u[t * NSLOT + w];
    int prio = (w == 0) ? 16 : (w - 1);            // event applied last; later neighbor wins
    int e = (t << 10) | (prio << 5) | w;
    unsigned hsh = hashrow(row);
    for (;;) {
        int cur = atomicCAS(&g_hrow[hsh], -1, row);
        if (cur == -1 || cur == row) {
            int c = atomicAdd(&g_hcnt[hsh], 1);
            if (c < HK) g_hent[hsh][c] = e;
            break;
        }
        hsh = (hsh + 1) & HMASK;
    }
}

__global__ void k_resolve(const int* __restrict__ u, const int* __restrict__ u_neg,
                          const float* __restrict__ z0, const float* __restrict__ time_bar,
                          const float* __restrict__ td) {
    int idx = blockIdx.x * blockDim.x + threadIdx.x;
    if (idx < 1088) prefetch_l2(td + idx * 32);    // whole td array
    if (idx >= BDIM * NREAD) return;
    int t = idx / NREAD, r = idx % NREAD;
    int row = (r < NSLOT) ? u[t * NSLOT + r] : u_neg[t * NEGK + (r - NSLOT)];
    if (r >= NSLOT) prefetch_l2(time_bar + (size_t)t * NNODES + row);
    unsigned hsh = hashrow(row);
    int src = -1, bestkey = -1;
    for (;;) {
        int cur = g_hrow[hsh];
        if (cur == -1) break;
        if (cur == row) {
            int c = g_hcnt[hsh]; if (c > HK) c = HK;
            for (int i = 0; i < c; ++i) {
                int e = g_hent[hsh][i];
                if ((e >> 10) < t) {
                    int key = e >> 5;
                    if (key > bestkey) { bestkey = key; src = ((e >> 10) << 5) | (e & 31); }
                }
            }
            break;
        }
        hsh = (hsh + 1) & HMASK;
    }
    g_src[t][r] = src;
    if (src >= 0) {
        if (r < NSLOT) atomicOr(&g_needed[src >> 5], 1 << (src & 31));
    } else {
        const float* p = z0 + (size_t)row * H;     // prefetch the z0 row
        #pragma unroll
        for (int l = 0; l < 8; ++l) prefetch_l2(p + l * 32);
    }
}

// Persistent main kernel: 256 threads/CTA, 2 CTAs/SM.
// ids [0,512): solo steps. [512,...): TMA-bulk z0->out copy chunks.
__global__ void __launch_bounds__(NTHR, 2) k_main(
    const int* __restrict__ u, const float* __restrict__ td,
    const float* __restrict__ z0,
    const float* __restrict__ bh,  const float* __restrict__ be2n,
    const float* __restrict__ bre, const float* __restrict__ brn,
    const float* __restrict__ Wt,  const float* __restrict__ bt,
    float* __restrict__ out)
{
    __shared__ __align__(16) float s_znb[DEG][H];
    __shared__ __align__(16) float s_emb[H];
    __shared__ __align__(16) float s_mean[H];
    __shared__ float s_td[NSLOT][4];
    __shared__ __align__(8) unsigned long long s_mbar[2];
    __shared__ int s_id;
    extern __shared__ __align__(16) char s_buf[];        // 2 x 32KB copy buffers

    const int tid  = threadIdx.x;              // == h (output column)
    const int lane = tid & 31, wid = tid >> 5;
    char* outzb = (char*)(out + (BDIM + BDIM * NEGK));
    const ulonglong2* BT_h   = (const ulonglong2*)g_BT[0];
    const ulonglong2* BT_e2n = (const ulonglong2*)g_BT[1];
    const ulonglong2* BT_re  = (const ulonglong2*)g_BT[2];
    const ulonglong2* BT_rn  = (const ulonglong2*)g_BT[3];

    // TMA copy state (only tid 0 uses)
    unsigned mb[2], sb[2], ph0 = 0, ph1 = 0;
    mb[0] = (unsigned)__cvta_generic_to_shared(&s_mbar[0]);
    mb[1] = (unsigned)__cvta_generic_to_shared(&s_mbar[1]);
    sb[0] = (unsigned)__cvta_generic_to_shared(s_buf);
    sb[1] = sb[0] + TILE;
    if (tid == 0) { mbar_init(mb[0], 1); mbar_init(mb[1], 1); }

    for (;;) {
        __syncthreads();                      // protect s_id / smem reuse; orders mbar init
        if (tid == 0) s_id = atomicAdd(&g_ctr, 1);
        __syncthreads();
        const int id = s_id;
        if (id >= TOTAL_WORK) break;

        // =================== TMA BULK COPY CHUNK ===================
        if (id >= BDIM) {
            if (tid == 0) {
                int chunk = id - BDIM;
                size_t byte0 = (size_t)chunk * CPR * H * 4;
                size_t total = (size_t)NNODES * H * 4;
                unsigned nb = (unsigned)(((total - byte0) < (size_t)(CPR * H * 4))
                                         ? (total - byte0) : (size_t)(CPR * H * 4));
                const char* src = (const char*)z0 + byte0;
                char*       dst = outzb + byte0;
                unsigned ntile = (nb + TILE - 1) / TILE;
                unsigned ph[2] = {ph0, ph1};
                // prime up to 2 loads
                for (unsigned i = 0; i < ntile && i < 2; ++i) {
                    unsigned tb = (i + 1 < ntile || nb % TILE == 0) ? TILE : nb % TILE;
                    if ((i + 1) * TILE <= nb) tb = TILE; else tb = nb - i * TILE;
                    mbar_expect(mb[i], tb);
                    bulk_g2s(sb[i], src + i * TILE, tb, mb[i]);
                }
                for (unsigned i = 0; i < ntile; ++i) {
                    unsigned b = i & 1;
                    unsigned tb = ((i + 1) * TILE <= nb) ? TILE : (nb - i * TILE);
                    mbar_wait(mb[b], ph[b]); ph[b] ^= 1;
                    bulk_s2g(dst + i * TILE, sb[b], tb);
                    asm volatile("cp.async.bulk.commit_group;" ::: "memory");
                    asm volatile("cp.async.bulk.wait_group 0;" ::: "memory");
                    if (i + 2 < ntile) {
                        unsigned nt = ((i + 3) * TILE <= nb) ? TILE : (nb - (i + 2) * TILE);
                        mbar_expect(mb[b], nt);
                        bulk_g2s(sb[b], src + (i + 2) * TILE, nt, mb[b]);
                    }
                }
                ph0 = ph[0]; ph1 = ph[1];
            }
            continue;
        }

        // =================== STEP s (solo; R8 structure) ===================
        const int s = id;

        if (tid < NSLOT) {                       // wait ONLY the 17 compute slots
            int sv = g_src[s][tid];
            if (sv >= 0) {
                int* flag = &g_done[sv >> 5];
                int bit = 1 << (sv & 31);
                while (!(ld_acq(flag) & bit)) __nanosleep(32);
            }
        }
        if (tid >= 32 && tid < 32 + NSLOT * 4) { // normalized time deltas
            int q = tid - 32;
            const float inv_sd[4] = {1.f/50.f, 1.f/7.f, 1.f/15.f, 1.f/15.f};
            s_td[q >> 2][q & 3] = td[(s * NSLOT + (q >> 2)) * 4 + (q & 3)] * inv_sd[q & 3];
        }
        __syncthreads();

        // load the 17 rows (emb_u + 16 neighbors); one warp per row
        for (int r = wid; r < NSLOT; r += 8) {
            int sv = g_src[s][r];
            const float4* src4 = (sv >= 0)
                ? (const float4*)g_staging[sv >> 5][sv & 31]
                : (const float4*)(z0 + (size_t)u[s * NSLOT + r] * H);
            float4* dst4 = (r == 0) ? (float4*)s_emb : (float4*)s_znb[r - 1];
            dst4[lane]      = src4[lane];
            dst4[lane + 32] = src4[lane + 32];
        }
        __syncthreads();

        // mean over 16 neighbor rows
        {
            float acc = 0.f;
            #pragma unroll
            for (int j = 0; j < DEG; ++j) acc += s_znb[j][tid];
            s_mean[tid] = acc * (1.0f / DEG);
        }
        __syncthreads();

        const int h = tid;
        const int need = g_needed[s];
        float4 wtr = *(const float4*)(Wt + (size_t)h * 4);
        float btv = bt[h];

        float cmn = matvec_bt(BT_e2n, h, s_emb) + be2n[h] + brn[h];
        bool zev_done = false;

        // ---------- PHASE 1: compute & publish only the needed slots ----------
        if (need) {
            if (need & 1) {
                float ah = matvec_bt(BT_h,  h, s_mean);
                float ae = matvec_bt(BT_re, h, s_emb);
                float tf0 = btv + wtr.x*s_td[0][0] + wtr.y*s_td[0][1]
                                + wtr.z*s_td[0][2] + wtr.w*s_td[0][3];
                g_staging[s][0][h] = sigmoidf_(ah + bh[h] + ae + bre[h] + tf0);
                zev_done = true;
            }
            for (int m = (need >> 1) & 0xFFFF; m; m &= (m - 1)) {
                int j = __ffs(m) - 1;
                float d = matvec_bt(BT_rn, h, s_znb[j]);
                float tf = btv + wtr.x*s_td[1+j][0] + wtr.y*s_td[1+j][1]
                               + wtr.z*s_td[1+j][2] + wtr.w*s_td[1+j][3];
                g_staging[s][1 + j][h] = sigmoidf_(d + cmn + tf);
            }
            __syncthreads();
            if (tid == 0) red_or_rel(&g_done[s], need);
        }

        // ---------- PHASE 2: remaining slots ----------
        if (!zev_done) {
            float ah = matvec_bt(BT_h,  h, s_mean);
            float ae = matvec_bt(BT_re, h, s_emb);
            float tf0 = btv + wtr.x*s_td[0][0] + wtr.y*s_td[0][1]
                            + wtr.z*s_td[0][2] + wtr.w*s_td[0][3];
            g_staging[s][0][h] = sigmoidf_(ah + bh[h] + ae + bre[h] + tf0);
        }
        {
            unsigned long long acc2[DEG];
            #pragma unroll
            for (int j = 0; j < DEG; ++j) acc2[j] = 0ull;
            for (int i4 = 0; i4 < H / 4; ++i4) {
                ulonglong2 w = BT_rn[i4 * H + h];
                #pragma unroll
                for (int j = 0; j < DEG; ++j) {
                    ulonglong2 z = *(const ulonglong2*)&s_znb[j][i4 * 4];
                    fma2(acc2[j], w.x, z.x); fma2(acc2[j], w.y, z.y);
                }
            }
            int skip = need >> 1;
            #pragma unroll
            for (int j = 0; j < DEG; ++j) {
                if (!((skip >> j) & 1)) {
                    float lo, hi; upk2(acc2[j], lo, hi);
                    float tf = btv + wtr.x*s_td[1+j][0] + wtr.y*s_td[1+j][1]
                                   + wtr.z*s_td[1+j][2] + wtr.w*s_td[1+j][3];
                    g_staging[s][1 + j][h] = sigmoidf_(lo + hi + cmn + tf);
                }
            }
        }
        __syncthreads();
        if (tid == 0) red_or_rel(&g_done[s], FULLMASK);
    }
}

// Post pass: one block per step. Hawkes lambdas (pos + 5 neg) and final scatter
// of last-writer rows over the copied z0 region. Runs after k_main completes.
__global__ void __launch_bounds__(NTHR) k_post(
    const int* __restrict__ u, const int* __restrict__ u_neg,
    const float* __restrict__ time_bar, const float* __restrict__ time_cur,
    const float* __restrict__ td, const float* __restrict__ z0,
    const float* __restrict__ Wom, const float* __restrict__ bom_p,
    const float* __restrict__ wt_p, const float* __restrict__ alpha_p,
    const float* __restrict__ psi_p, float* __restrict__ out)
{
    const int s = blockIdx.x;
    const int tid = threadIdx.x, lane = tid & 31, wid = tid >> 5;
    const float w_t = *wt_p, alpha = *alpha_p, psi = *psi_p, bom = *bom_p;
    const float inv_psi = 1.0f / (psi + 1e-7f);
    float* outz = out + (BDIM + BDIM * NEGK);

    if (wid < NEGK) {                            // negative lambdas
        int node = u_neg[s * NEGK + wid];
        int sv = g_src[s][NSLOT + wid];
        const float* srcp = (sv >= 0) ? g_staging[sv >> 5][sv & 31]
                                      : (z0 + (size_t)node * H);
        float acc = 0.f;
        for (int i = lane; i < H; i += 32) acc += srcp[i] * Wom[i];
        #pragma unroll
        for (int o = 16; o; o >>= 1) acc += __shfl_down_sync(0xffffffffu, acc, o);
        if (lane == 0) {
            float ts = time_cur[s] - time_bar[(size_t)s * NNODES + node];
            float g = acc + bom + alpha * expf(-w_t * (ts * (1.0f / 86400.0f)));
            float gp = fminf(fmaxf(g * inv_psi, -75.f), 75.f);
            out[BDIM + s * NEGK + wid] = psi * log1pf(expf(gp)) * (1.0f / NEGK);
        }
    } else if (wid == 5) {                       // positive lambda
        int sv = g_src[s][0];
        const float* srcp = (sv >= 0) ? g_staging[sv >> 5][sv & 31]
                                      : (z0 + (size_t)u[s * NSLOT] * H);
        float acc = 0.f;
        for (int i = lane; i < H; i += 32) acc += srcp[i] * Wom[i];
        #pragma unroll
        for (int o = 16; o; o >>= 1) acc += __shfl_down_sync(0xffffffffu, acc, o);
        if (lane == 0) {
            float ts = time_cur[s] - td[s * NSLOT * 4] * (1.0f / 50.0f);
            float g = acc + bom + alpha * expf(-w_t * (ts * (1.0f / 86400.0f)));
            float gp = fminf(fmaxf(g * inv_psi, -75.f), 75.f);
            out[s] = psi * log1pf(expf(gp));
        }
    }

    // scatter: warp handles slots wid, wid+8, wid+16
    for (int w = wid; w < NSLOT; w += 8) {
        int row = u[s * NSLOT + w];
        unsigned hsh = hashrow(row);
        int beste = -1, bestkey = -1;
        for (;;) {
            int cur = g_hrow[hsh];
            if (cur == -1) break;
            if (cur == row) {
                int c = g_hcnt[hsh]; if (c > HK) c = HK;
                for (int i = 0; i < c; ++i) {
                    int e = g_hent[hsh][i];
                    int key = e >> 5;
                    if (key > bestkey) { bestkey = key; beste = e; }
                }
                break;
            }
            hsh = (hsh + 1) & HMASK;
        }
        int prio = (w == 0) ? 16 : (w - 1);
        if (beste == ((s << 10) | (prio << 5) | w)) {   // this (s,w) is the last writer
            const float4* src = (const float4*)g_staging[s][w];
            float4* dst = (float4*)outz + (size_t)row * (H / 4);
            dst[lane]      = src[lane];
            dst[lane + 32] = src[lane + 32];
        }
    }
}

// ------------------------------- launch ------------------------------------
extern "C" void kernel_launch(void* const* d_in, const int* in_sizes, int n_in,
                              void* d_out, int out_size) {
    const int*   u     = (const int*)  d_in[0];
    const float* td    = (const float*)d_in[1];
    const float* tbar  = (const float*)d_in[2];
    const float* tcur  = (const float*)d_in[3];
    // d_in[4] significance, d_in[5] magnitudo: unused by reference
    const int*   uneg  = (const int*)  d_in[6];
    const float* z0    = (const float*)d_in[7];
    const float* Wh    = (const float*)d_in[8];
    const float* bh    = (const float*)d_in[9];
    const float* We2n  = (const float*)d_in[10];
    const float* be2n  = (const float*)d_in[11];
    const float* Wre   = (const float*)d_in[12];
    const float* bre   = (const float*)d_in[13];
    const float* Wrn   = (const float*)d_in[14];
    const float* brn   = (const float*)d_in[15];
    const float* Wt    = (const float*)d_in[16];
    const float* bt    = (const float*)d_in[17];
    const float* Wom   = (const float*)d_in[18];
    const float* bom   = (const float*)d_in[19];
    const float* wt    = (const float*)d_in[20];
    const float* alpha = (const float*)d_in[21];
    const float* psi   = (const float*)d_in[22];
    float* out = (float*)d_out;

    static int attr_set = 0;
    if (!attr_set) {
        cudaFuncSetAttribute(k_main, cudaFuncAttributeMaxDynamicSharedMemorySize, DSMEM);
        attr_set = 1;
    }

    k_prep   <<<256, 256>>>(Wh, We2n, Wre, Wrn);
    k_insert <<<(BDIM * NSLOT + 255) / 256, 256>>>(u);
    k_resolve<<<(BDIM * NREAD + 255) / 256, 256>>>(u, uneg, z0, tbar, td);

    int dev = 0, nsm = 148;
    cudaGetDevice(&dev);
    cudaDeviceGetAttribute(&nsm, cudaDevAttrMultiProcessorCount, dev);

    k_main<<<nsm * 2, NTHR, DSMEM>>>(u, td, z0, bh, be2n, bre, brn, Wt, bt, out);

    k_post<<<BDIM, NTHR>>>(u, uneg, tbar, tcur, td, z0,
                           Wom, bom, wt, alpha, psi, out);
}